// round 1
// baseline (speedup 1.0000x reference)
#include <cuda_runtime.h>

#define NN 100000
#define NE 1600000
#define DH 128

// ---- scratch (static __device__ globals; no allocation allowed) ----
__device__ float g_deg[NN];
__device__ float g_agg[NN * DH];
__device__ float g_h1[NN * DH];
__device__ float g_h2[NN * DH];

// ---- degree ----
__global__ void deg_count_kernel(const int* __restrict__ dst, float* __restrict__ deg) {
    int i = blockIdx.x * blockDim.x + threadIdx.x;
    if (i < NE) atomicAdd(&deg[dst[i]], 1.0f);
}

__global__ void deg_inv_kernel(float* deg) {
    int i = blockIdx.x * blockDim.x + threadIdx.x;
    if (i < NN) {
        float d = deg[i];
        deg[i] = d > 0.0f ? 1.0f / d : 0.0f;
    }
}

// ---- scatter: one warp per edge, red.v4 atomics into agg ----
__global__ void scatter_kernel(const float* __restrict__ xin,
                               const int* __restrict__ src,
                               const int* __restrict__ dst,
                               const float* __restrict__ w,
                               float* __restrict__ agg) {
    unsigned gt = blockIdx.x * blockDim.x + threadIdx.x;
    unsigned e = gt >> 5;
    int lane = threadIdx.x & 31;
    if (e >= NE) return;
    int s   = __ldg(src + e);
    int d   = __ldg(dst + e);
    float wt = __ldg(w + e);
    float4 v = *reinterpret_cast<const float4*>(xin + (size_t)s * DH + lane * 4);
    v.x *= wt; v.y *= wt; v.z *= wt; v.w *= wt;
    float* p = agg + (size_t)d * DH + lane * 4;
    asm volatile("red.global.add.v4.f32 [%0], {%1,%2,%3,%4};"
                 :: "l"(p), "f"(v.x), "f"(v.y), "f"(v.z), "f"(v.w)
                 : "memory");
}

// ---- fused GEMM: out = relu( (deginv*agg) @ Wrel + b + xin @ Wroot ) ----
// C[N,128] = A[N,256] @ B[256,128], B = [Wrel; Wroot] held entirely in smem.
// Block: 64 rows (nodes) x 128 cols; 256 threads; thread tile 8x4.
__global__ void __launch_bounds__(256) gemm_fused_kernel(
    const float* __restrict__ agg, const float* __restrict__ xin,
    const float* __restrict__ Wrel, const float* __restrict__ Wroot,
    const float* __restrict__ bias, const float* __restrict__ deginv,
    float* __restrict__ out)
{
    extern __shared__ float smem[];
    float* Bs = smem;             // [256][128]
    float* As = smem + 256 * DH;  // [64][32]
    const int tid = threadIdx.x;

    // Copy B = [Wrel; Wroot] to smem (float4, coalesced)
    const float4* wr4 = reinterpret_cast<const float4*>(Wrel);
    const float4* wo4 = reinterpret_cast<const float4*>(Wroot);
    float4* b4 = reinterpret_cast<float4*>(Bs);
    #pragma unroll
    for (int i = tid; i < DH * DH / 4; i += 256) {
        b4[i]                 = wr4[i];
        b4[i + DH * DH / 4]   = wo4[i];
    }

    const int row0 = blockIdx.x * 64;
    const int ty = tid >> 5;   // 0..7  -> 8 rows each
    const int tx = tid & 31;   // 0..31 -> 4 cols each

    float acc[8][4];
    #pragma unroll
    for (int i = 0; i < 8; i++) {
        acc[i][0] = 0.f; acc[i][1] = 0.f; acc[i][2] = 0.f; acc[i][3] = 0.f;
    }

    for (int kc = 0; kc < 2 * DH; kc += 32) {
        __syncthreads();  // prior-iter reads done (first iter: covers B copy too)
        // Load A tile [64 rows][32 k] : k<128 -> agg*deginv ; k>=128 -> xin
        #pragma unroll
        for (int f = tid; f < 512; f += 256) {
            int r  = f >> 3;
            int k4 = f & 7;
            int grow = row0 + r;
            int gk   = kc + k4 * 4;
            float4 v = make_float4(0.f, 0.f, 0.f, 0.f);
            if (grow < NN) {
                if (gk < DH) {
                    v = *reinterpret_cast<const float4*>(agg + (size_t)grow * DH + gk);
                    float di = deginv[grow];
                    v.x *= di; v.y *= di; v.z *= di; v.w *= di;
                } else {
                    v = *reinterpret_cast<const float4*>(xin + (size_t)grow * DH + (gk - DH));
                }
            }
            *reinterpret_cast<float4*>(As + r * 32 + k4 * 4) = v;
        }
        __syncthreads();

        #pragma unroll
        for (int k = 0; k < 32; k++) {
            float4 b = *reinterpret_cast<const float4*>(Bs + (kc + k) * DH + tx * 4);
            #pragma unroll
            for (int i = 0; i < 8; i++) {
                float a = As[(ty * 8 + i) * 32 + k];  // warp-uniform -> LDS broadcast
                acc[i][0] = fmaf(a, b.x, acc[i][0]);
                acc[i][1] = fmaf(a, b.y, acc[i][1]);
                acc[i][2] = fmaf(a, b.z, acc[i][2]);
                acc[i][3] = fmaf(a, b.w, acc[i][3]);
            }
        }
    }

    float4 bb = *reinterpret_cast<const float4*>(bias + tx * 4);
    #pragma unroll
    for (int i = 0; i < 8; i++) {
        int grow = row0 + ty * 8 + i;
        if (grow < NN) {
            float4 o;
            o.x = fmaxf(acc[i][0] + bb.x, 0.f);
            o.y = fmaxf(acc[i][1] + bb.y, 0.f);
            o.z = fmaxf(acc[i][2] + bb.z, 0.f);
            o.w = fmaxf(acc[i][3] + bb.w, 0.f);
            *reinterpret_cast<float4*>(out + (size_t)grow * DH + tx * 4) = o;
        }
    }
}

extern "C" void kernel_launch(void* const* d_in, const int* in_sizes, int n_in,
                              void* d_out, int out_size) {
    const float* x      = (const float*)d_in[0];
    const int*   ei     = (const int*)d_in[1];
    const float* ea     = (const float*)d_in[2];
    const float* Wrel1  = (const float*)d_in[3];
    const float* b1     = (const float*)d_in[4];
    const float* Wroot1 = (const float*)d_in[5];
    const float* Wrel2  = (const float*)d_in[6];
    const float* b2     = (const float*)d_in[7];
    const float* Wroot2 = (const float*)d_in[8];
    const float* Wrel3  = (const float*)d_in[9];
    const float* b3     = (const float*)d_in[10];
    const float* Wroot3 = (const float*)d_in[11];
    float* out = (float*)d_out;

    const int* src = ei;        // edge_index[0]
    const int* dst = ei + NE;   // edge_index[1]

    float *deg, *agg, *h1, *h2;
    cudaGetSymbolAddress((void**)&deg, g_deg);
    cudaGetSymbolAddress((void**)&agg, g_agg);
    cudaGetSymbolAddress((void**)&h1,  g_h1);
    cudaGetSymbolAddress((void**)&h2,  g_h2);

    size_t smem = (256 * DH + 64 * 32) * sizeof(float);  // 139264 B
    cudaFuncSetAttribute(gemm_fused_kernel,
                         cudaFuncAttributeMaxDynamicSharedMemorySize, (int)smem);

    // degree -> deg_inv (once; reused by all 3 layers)
    cudaMemsetAsync(deg, 0, NN * sizeof(float));
    deg_count_kernel<<<(NE + 255) / 256, 256>>>(dst, deg);
    deg_inv_kernel<<<(NN + 255) / 256, 256>>>(deg);

    const float* Wr[3] = {Wrel1, Wrel2, Wrel3};
    const float* Wo[3] = {Wroot1, Wroot2, Wroot3};
    const float* bv[3] = {b1, b2, b3};
    float* outs[3] = {h1, h2, out};

    const float* cur = x;
    int scatter_blocks = (NE * 32 + 255) / 256;  // one warp per edge
    for (int l = 0; l < 3; l++) {
        cudaMemsetAsync(agg, 0, (size_t)NN * DH * sizeof(float));
        scatter_kernel<<<scatter_blocks, 256>>>(cur, src, dst, ea, agg);
        gemm_fused_kernel<<<(NN + 63) / 64, 256, smem>>>(
            agg, cur, Wr[l], Wo[l], bv[l], deg, outs[l]);
        cur = outs[l];
    }
}

// round 2
// speedup vs baseline: 1.4611x; 1.4611x over previous
#include <cuda_runtime.h>

#define NN 100000
#define NE 1600000
#define DH 128

// ---- scratch ----
__device__ int   g_deg[NN];
__device__ int   g_rowptr[NN + 1];
__device__ int   g_cursor[NN];
__device__ int   g_csr_src[NE];
__device__ float g_csr_w[NE];
__device__ float g_agg[NN * DH];
__device__ float g_h1[NN * DH];
__device__ float g_h2[NN * DH];

// ---- CSR build ----
__global__ void deg_count_kernel(const int* __restrict__ dst, int* __restrict__ deg) {
    int i = blockIdx.x * blockDim.x + threadIdx.x;
    if (i < NE) atomicAdd(&deg[dst[i]], 1);
}

// single-block exclusive scan of deg -> rowptr (+ copy to cursor)
__global__ void scan_kernel(const int* __restrict__ deg,
                            int* __restrict__ rowptr, int* __restrict__ cursor) {
    __shared__ int sdata[1024];
    __shared__ int carry;
    if (threadIdx.x == 0) carry = 0;
    __syncthreads();
    for (int base = 0; base < NN; base += 1024) {
        int i = base + (int)threadIdx.x;
        int v = (i < NN) ? deg[i] : 0;
        sdata[threadIdx.x] = v;
        __syncthreads();
        #pragma unroll
        for (int off = 1; off < 1024; off <<= 1) {
            int t = (threadIdx.x >= off) ? sdata[threadIdx.x - off] : 0;
            __syncthreads();
            sdata[threadIdx.x] += t;
            __syncthreads();
        }
        int excl = sdata[threadIdx.x] - v + carry;
        if (i < NN) { rowptr[i] = excl; cursor[i] = excl; }
        __syncthreads();
        if (threadIdx.x == 0) carry += sdata[1023];
        __syncthreads();
    }
    if (threadIdx.x == 0) rowptr[NN] = carry;
}

__global__ void fill_csr_kernel(const int* __restrict__ src, const int* __restrict__ dst,
                                const float* __restrict__ w, int* __restrict__ cursor,
                                int* __restrict__ csr_src, float* __restrict__ csr_w) {
    int e = blockIdx.x * blockDim.x + threadIdx.x;
    if (e < NE) {
        int d = dst[e];
        int p = atomicAdd(&cursor[d], 1);
        csr_src[p] = src[e];
        csr_w[p]   = w[e];
    }
}

// ---- aggregation: one warp per node, gather over in-edges, mean fused ----
__global__ void gather_agg_kernel(const float* __restrict__ xin,
                                  const int* __restrict__ rowptr,
                                  const int* __restrict__ csr_src,
                                  const float* __restrict__ csr_w,
                                  float* __restrict__ agg) {
    unsigned gt = blockIdx.x * blockDim.x + threadIdx.x;
    unsigned node = gt >> 5;
    int lane = threadIdx.x & 31;
    if (node >= NN) return;
    int s0 = __ldg(rowptr + node);
    int s1 = __ldg(rowptr + node + 1);
    float4 acc = make_float4(0.f, 0.f, 0.f, 0.f);
    int e = s0;
    // 2-wide to improve MLP
    for (; e + 1 < s1; e += 2) {
        int   sa = __ldg(csr_src + e);
        int   sb = __ldg(csr_src + e + 1);
        float wa = __ldg(csr_w + e);
        float wb = __ldg(csr_w + e + 1);
        float4 va = *reinterpret_cast<const float4*>(xin + (size_t)sa * DH + lane * 4);
        float4 vb = *reinterpret_cast<const float4*>(xin + (size_t)sb * DH + lane * 4);
        acc.x = fmaf(wa, va.x, acc.x); acc.y = fmaf(wa, va.y, acc.y);
        acc.z = fmaf(wa, va.z, acc.z); acc.w = fmaf(wa, va.w, acc.w);
        acc.x = fmaf(wb, vb.x, acc.x); acc.y = fmaf(wb, vb.y, acc.y);
        acc.z = fmaf(wb, vb.z, acc.z); acc.w = fmaf(wb, vb.w, acc.w);
    }
    if (e < s1) {
        int   sa = __ldg(csr_src + e);
        float wa = __ldg(csr_w + e);
        float4 va = *reinterpret_cast<const float4*>(xin + (size_t)sa * DH + lane * 4);
        acc.x = fmaf(wa, va.x, acc.x); acc.y = fmaf(wa, va.y, acc.y);
        acc.z = fmaf(wa, va.z, acc.z); acc.w = fmaf(wa, va.w, acc.w);
    }
    float di = (s1 > s0) ? 1.0f / (float)(s1 - s0) : 0.f;
    acc.x *= di; acc.y *= di; acc.z *= di; acc.w *= di;
    *reinterpret_cast<float4*>(agg + (size_t)node * DH + lane * 4) = acc;
}

// ---- fused GEMM: out = relu( agg@Wrel + b + xin@Wroot ) ----
// A[N,256] = [agg | xin], B[256,128] = [Wrel ; Wroot].
// Tile: 64 rows x 128 cols, 256 threads, double-buffered 32-k tiles, 48KB smem.
__global__ void __launch_bounds__(256, 3) gemm_fused_kernel(
    const float* __restrict__ agg, const float* __restrict__ xin,
    const float* __restrict__ Wrel, const float* __restrict__ Wroot,
    const float* __restrict__ bias, float* __restrict__ out)
{
    __shared__ float As[2][64 * 32];   // 16 KB
    __shared__ float Bs[2][32 * 128];  // 32 KB
    const int tid  = threadIdx.x;
    const int w    = tid >> 5;   // 0..7 -> rows w*8..w*8+7
    const int lane = tid & 31;   // cols lane*4..lane*4+3
    const int row0 = blockIdx.x * 64;

    float4 ra[2], rb[4];

    auto ldg_tiles = [&](int it) {
        #pragma unroll
        for (int j = 0; j < 2; j++) {          // A: 64x32 = 512 float4
            int f = tid + j * 256;
            int r = f >> 3, k4 = f & 7;
            int grow = row0 + r;
            int gk = it * 32 + k4 * 4;
            float4 v = make_float4(0.f, 0.f, 0.f, 0.f);
            if (grow < NN) {
                if (gk < DH) v = *reinterpret_cast<const float4*>(agg + (size_t)grow * DH + gk);
                else         v = *reinterpret_cast<const float4*>(xin + (size_t)grow * DH + (gk - DH));
            }
            ra[j] = v;
        }
        #pragma unroll
        for (int j = 0; j < 4; j++) {          // B: 32x128 = 1024 float4
            int f = tid + j * 256;
            int kr = it * 32 + (f >> 5);
            int c  = (f & 31) * 4;
            float4 v;
            if (kr < DH) v = *reinterpret_cast<const float4*>(Wrel  + (size_t)kr * DH + c);
            else         v = *reinterpret_cast<const float4*>(Wroot + (size_t)(kr - DH) * DH + c);
            rb[j] = v;
        }
    };
    auto sts_tiles = [&](int buf) {
        #pragma unroll
        for (int j = 0; j < 2; j++) {
            int f = tid + j * 256;
            *reinterpret_cast<float4*>(&As[buf][f * 4]) = ra[j];
        }
        #pragma unroll
        for (int j = 0; j < 4; j++) {
            int f = tid + j * 256;
            *reinterpret_cast<float4*>(&Bs[buf][f * 4]) = rb[j];
        }
    };

    float acc[8][4];
    #pragma unroll
    for (int i = 0; i < 8; i++) { acc[i][0]=0.f; acc[i][1]=0.f; acc[i][2]=0.f; acc[i][3]=0.f; }

    ldg_tiles(0);
    sts_tiles(0);
    __syncthreads();

    #pragma unroll
    for (int it = 0; it < 8; it++) {
        int buf = it & 1;
        if (it < 7) ldg_tiles(it + 1);
        #pragma unroll
        for (int k = 0; k < 32; k++) {
            float4 b = *reinterpret_cast<const float4*>(&Bs[buf][k * 128 + lane * 4]);
            #pragma unroll
            for (int i = 0; i < 8; i++) {
                float a = As[buf][(w * 8 + i) * 32 + k];  // warp-uniform broadcast
                acc[i][0] = fmaf(a, b.x, acc[i][0]);
                acc[i][1] = fmaf(a, b.y, acc[i][1]);
                acc[i][2] = fmaf(a, b.z, acc[i][2]);
                acc[i][3] = fmaf(a, b.w, acc[i][3]);
            }
        }
        if (it < 7) {
            sts_tiles(buf ^ 1);
            __syncthreads();
        }
    }

    float4 bb = *reinterpret_cast<const float4*>(bias + lane * 4);
    #pragma unroll
    for (int i = 0; i < 8; i++) {
        int grow = row0 + w * 8 + i;
        if (grow < NN) {
            float4 o;
            o.x = fmaxf(acc[i][0] + bb.x, 0.f);
            o.y = fmaxf(acc[i][1] + bb.y, 0.f);
            o.z = fmaxf(acc[i][2] + bb.z, 0.f);
            o.w = fmaxf(acc[i][3] + bb.w, 0.f);
            *reinterpret_cast<float4*>(out + (size_t)grow * DH + lane * 4) = o;
        }
    }
}

extern "C" void kernel_launch(void* const* d_in, const int* in_sizes, int n_in,
                              void* d_out, int out_size) {
    const float* x      = (const float*)d_in[0];
    const int*   ei     = (const int*)d_in[1];
    const float* ea     = (const float*)d_in[2];
    const float* Wrel1  = (const float*)d_in[3];
    const float* b1     = (const float*)d_in[4];
    const float* Wroot1 = (const float*)d_in[5];
    const float* Wrel2  = (const float*)d_in[6];
    const float* b2     = (const float*)d_in[7];
    const float* Wroot2 = (const float*)d_in[8];
    const float* Wrel3  = (const float*)d_in[9];
    const float* b3     = (const float*)d_in[10];
    const float* Wroot3 = (const float*)d_in[11];
    float* out = (float*)d_out;

    const int* src = ei;
    const int* dst = ei + NE;

    int *deg, *rowptr, *cursor, *csr_src;
    float *csr_w, *agg, *h1, *h2;
    cudaGetSymbolAddress((void**)&deg,     g_deg);
    cudaGetSymbolAddress((void**)&rowptr,  g_rowptr);
    cudaGetSymbolAddress((void**)&cursor,  g_cursor);
    cudaGetSymbolAddress((void**)&csr_src, g_csr_src);
    cudaGetSymbolAddress((void**)&csr_w,   g_csr_w);
    cudaGetSymbolAddress((void**)&agg,     g_agg);
    cudaGetSymbolAddress((void**)&h1,      g_h1);
    cudaGetSymbolAddress((void**)&h2,      g_h2);

    // CSR build (once; reused by all 3 layers)
    cudaMemsetAsync(deg, 0, NN * sizeof(int));
    deg_count_kernel<<<(NE + 255) / 256, 256>>>(dst, deg);
    scan_kernel<<<1, 1024>>>(deg, rowptr, cursor);
    fill_csr_kernel<<<(NE + 255) / 256, 256>>>(src, dst, ea, cursor, csr_src, csr_w);

    const float* Wr[3] = {Wrel1, Wrel2, Wrel3};
    const float* Wo[3] = {Wroot1, Wroot2, Wroot3};
    const float* bv[3] = {b1, b2, b3};
    float* outs[3] = {h1, h2, out};

    const float* cur = x;
    int gather_blocks = (NN * 32 + 255) / 256;
    for (int l = 0; l < 3; l++) {
        gather_agg_kernel<<<gather_blocks, 256>>>(cur, rowptr, csr_src, csr_w, agg);
        gemm_fused_kernel<<<(NN + 63) / 64, 256>>>(agg, cur, Wr[l], Wo[l], bv[l], outs[l]);
        cur = outs[l];
    }
}

// round 3
// speedup vs baseline: 1.6874x; 1.1549x over previous
#include <cuda_runtime.h>

#define NN 100000
#define NE 1600000
#define DH 128
#define KT 16

// ---- scratch ----
__device__ int   g_deg[NN];
__device__ int   g_rowptr[NN + 1];
__device__ int   g_cursor[NN];
__device__ int   g_csr_src[NE];
__device__ float g_csr_w[NE];
__device__ float g_agg[NN * DH];
__device__ float g_h1[NN * DH];
__device__ float g_h2[NN * DH];

// ---- CSR build ----
__global__ void deg_count_kernel(const int* __restrict__ dst, int* __restrict__ deg) {
    int i = blockIdx.x * blockDim.x + threadIdx.x;
    if (i < NE) atomicAdd(&deg[dst[i]], 1);
}

__global__ void scan_kernel(const int* __restrict__ deg,
                            int* __restrict__ rowptr, int* __restrict__ cursor) {
    __shared__ int sdata[1024];
    __shared__ int carry;
    if (threadIdx.x == 0) carry = 0;
    __syncthreads();
    for (int base = 0; base < NN; base += 1024) {
        int i = base + (int)threadIdx.x;
        int v = (i < NN) ? deg[i] : 0;
        sdata[threadIdx.x] = v;
        __syncthreads();
        #pragma unroll
        for (int off = 1; off < 1024; off <<= 1) {
            int t = (threadIdx.x >= off) ? sdata[threadIdx.x - off] : 0;
            __syncthreads();
            sdata[threadIdx.x] += t;
            __syncthreads();
        }
        int excl = sdata[threadIdx.x] - v + carry;
        if (i < NN) { rowptr[i] = excl; cursor[i] = excl; }
        __syncthreads();
        if (threadIdx.x == 0) carry += sdata[1023];
        __syncthreads();
    }
    if (threadIdx.x == 0) rowptr[NN] = carry;
}

__global__ void fill_csr_kernel(const int* __restrict__ src, const int* __restrict__ dst,
                                const float* __restrict__ w, int* __restrict__ cursor,
                                int* __restrict__ csr_src, float* __restrict__ csr_w) {
    int e = blockIdx.x * blockDim.x + threadIdx.x;
    if (e < NE) {
        int d = dst[e];
        int p = atomicAdd(&cursor[d], 1);
        csr_src[p] = src[e];
        csr_w[p]   = w[e];
    }
}

// ---- aggregation: one warp per node, gather, mean fused ----
__global__ void gather_agg_kernel(const float* __restrict__ xin,
                                  const int* __restrict__ rowptr,
                                  const int* __restrict__ csr_src,
                                  const float* __restrict__ csr_w,
                                  float* __restrict__ agg) {
    unsigned gt = blockIdx.x * blockDim.x + threadIdx.x;
    unsigned node = gt >> 5;
    int lane = threadIdx.x & 31;
    if (node >= NN) return;
    int s0 = __ldg(rowptr + node);
    int s1 = __ldg(rowptr + node + 1);
    float4 acc = make_float4(0.f, 0.f, 0.f, 0.f);
    int e = s0;
    for (; e + 3 < s1; e += 4) {
        int   s_[4]; float w_[4];
        #pragma unroll
        for (int q = 0; q < 4; q++) { s_[q] = __ldg(csr_src + e + q); w_[q] = __ldg(csr_w + e + q); }
        float4 v_[4];
        #pragma unroll
        for (int q = 0; q < 4; q++)
            v_[q] = *reinterpret_cast<const float4*>(xin + (size_t)s_[q] * DH + lane * 4);
        #pragma unroll
        for (int q = 0; q < 4; q++) {
            acc.x = fmaf(w_[q], v_[q].x, acc.x); acc.y = fmaf(w_[q], v_[q].y, acc.y);
            acc.z = fmaf(w_[q], v_[q].z, acc.z); acc.w = fmaf(w_[q], v_[q].w, acc.w);
        }
    }
    for (; e < s1; e++) {
        int   sa = __ldg(csr_src + e);
        float wa = __ldg(csr_w + e);
        float4 va = *reinterpret_cast<const float4*>(xin + (size_t)sa * DH + lane * 4);
        acc.x = fmaf(wa, va.x, acc.x); acc.y = fmaf(wa, va.y, acc.y);
        acc.z = fmaf(wa, va.z, acc.z); acc.w = fmaf(wa, va.w, acc.w);
    }
    float di = (s1 > s0) ? 1.0f / (float)(s1 - s0) : 0.f;
    acc.x *= di; acc.y *= di; acc.z *= di; acc.w *= di;
    *reinterpret_cast<float4*>(agg + (size_t)node * DH + lane * 4) = acc;
}

// ---- fused GEMM: out = relu( agg@Wrel + b + xin@Wroot ) ----
// C[128 x 128] tile per block, 256 threads, 8x8 micro-tile, KT=16 double-buffered.
// A slices stored k-major (transposed) in smem: AsT[k][row], row-pad 132.
__global__ void __launch_bounds__(256, 2) gemm_fused_kernel(
    const float* __restrict__ agg, const float* __restrict__ xin,
    const float* __restrict__ Wrel, const float* __restrict__ Wroot,
    const float* __restrict__ bias, float* __restrict__ out)
{
    __shared__ float AsT[2][KT * 132];   // 2 * 8448 B
    __shared__ float Bs [2][KT * 128];   // 2 * 8192 B
    const int tid = threadIdx.x;
    const int tx  = tid & 15;   // col group: cols tx*4..+3 and 64+tx*4..+3
    const int ty  = tid >> 4;   // row group: rows ty*8..+7
    const int row0 = blockIdx.x * 128;

    float4 ra[2], rb[2];

    auto ldg = [&](int it) {
        const float* abase = (it < 8) ? agg  : xin;
        const float* bbase = (it < 8) ? Wrel : Wroot;
        const int k0 = (it & 7) * KT;
        #pragma unroll
        for (int j = 0; j < 2; j++) {
            int f = tid + j * 256;
            int r = f >> 2, kq = f & 3;               // A: row r, k-quad kq
            int grow = row0 + r;
            float4 v = make_float4(0.f, 0.f, 0.f, 0.f);
            if (grow < NN)
                v = *reinterpret_cast<const float4*>(abase + (size_t)grow * DH + k0 + kq * 4);
            ra[j] = v;
            int krl = f >> 5, c = (f & 31) * 4;       // B: k-row krl, col c
            rb[j] = *reinterpret_cast<const float4*>(bbase + (size_t)(k0 + krl) * DH + c);
        }
    };
    auto sts = [&](int buf) {
        #pragma unroll
        for (int j = 0; j < 2; j++) {
            int f = tid + j * 256;
            int r = f >> 2, kq = f & 3;
            float* p = &AsT[buf][(kq * 4) * 132 + r]; // transpose: 4 scalar stores
            p[0]   = ra[j].x;
            p[132] = ra[j].y;
            p[264] = ra[j].z;
            p[396] = ra[j].w;
            int krl = f >> 5, c = (f & 31) * 4;
            *reinterpret_cast<float4*>(&Bs[buf][krl * 128 + c]) = rb[j];
        }
    };

    float acc[8][8];
    #pragma unroll
    for (int i = 0; i < 8; i++)
        #pragma unroll
        for (int j = 0; j < 8; j++) acc[i][j] = 0.f;

    ldg(0);
    sts(0);
    __syncthreads();

    #pragma unroll 1
    for (int it = 0; it < 16; it++) {
        const int buf = it & 1;
        if (it < 15) ldg(it + 1);
        #pragma unroll
        for (int k = 0; k < KT; k++) {
            float4 a0 = *reinterpret_cast<const float4*>(&AsT[buf][k * 132 + ty * 8]);
            float4 a1 = *reinterpret_cast<const float4*>(&AsT[buf][k * 132 + ty * 8 + 4]);
            float4 b0 = *reinterpret_cast<const float4*>(&Bs[buf][k * 128 + tx * 4]);
            float4 b1 = *reinterpret_cast<const float4*>(&Bs[buf][k * 128 + 64 + tx * 4]);
            float av[8] = {a0.x, a0.y, a0.z, a0.w, a1.x, a1.y, a1.z, a1.w};
            float bv[8] = {b0.x, b0.y, b0.z, b0.w, b1.x, b1.y, b1.z, b1.w};
            #pragma unroll
            for (int i = 0; i < 8; i++)
                #pragma unroll
                for (int j = 0; j < 8; j++)
                    acc[i][j] = fmaf(av[i], bv[j], acc[i][j]);
        }
        if (it < 15) {
            sts(buf ^ 1);
            __syncthreads();
        }
    }

    float4 bb0 = *reinterpret_cast<const float4*>(bias + tx * 4);
    float4 bb1 = *reinterpret_cast<const float4*>(bias + 64 + tx * 4);
    #pragma unroll
    for (int i = 0; i < 8; i++) {
        int grow = row0 + ty * 8 + i;
        if (grow < NN) {
            float4 o0, o1;
            o0.x = fmaxf(acc[i][0] + bb0.x, 0.f);
            o0.y = fmaxf(acc[i][1] + bb0.y, 0.f);
            o0.z = fmaxf(acc[i][2] + bb0.z, 0.f);
            o0.w = fmaxf(acc[i][3] + bb0.w, 0.f);
            o1.x = fmaxf(acc[i][4] + bb1.x, 0.f);
            o1.y = fmaxf(acc[i][5] + bb1.y, 0.f);
            o1.z = fmaxf(acc[i][6] + bb1.z, 0.f);
            o1.w = fmaxf(acc[i][7] + bb1.w, 0.f);
            *reinterpret_cast<float4*>(out + (size_t)grow * DH + tx * 4)      = o0;
            *reinterpret_cast<float4*>(out + (size_t)grow * DH + 64 + tx * 4) = o1;
        }
    }
}

extern "C" void kernel_launch(void* const* d_in, const int* in_sizes, int n_in,
                              void* d_out, int out_size) {
    const float* x      = (const float*)d_in[0];
    const int*   ei     = (const int*)d_in[1];
    const float* ea     = (const float*)d_in[2];
    const float* Wrel1  = (const float*)d_in[3];
    const float* b1     = (const float*)d_in[4];
    const float* Wroot1 = (const float*)d_in[5];
    const float* Wrel2  = (const float*)d_in[6];
    const float* b2     = (const float*)d_in[7];
    const float* Wroot2 = (const float*)d_in[8];
    const float* Wrel3  = (const float*)d_in[9];
    const float* b3     = (const float*)d_in[10];
    const float* Wroot3 = (const float*)d_in[11];
    float* out = (float*)d_out;

    const int* src = ei;
    const int* dst = ei + NE;

    int *deg, *rowptr, *cursor, *csr_src;
    float *csr_w, *agg, *h1, *h2;
    cudaGetSymbolAddress((void**)&deg,     g_deg);
    cudaGetSymbolAddress((void**)&rowptr,  g_rowptr);
    cudaGetSymbolAddress((void**)&cursor,  g_cursor);
    cudaGetSymbolAddress((void**)&csr_src, g_csr_src);
    cudaGetSymbolAddress((void**)&csr_w,   g_csr_w);
    cudaGetSymbolAddress((void**)&agg,     g_agg);
    cudaGetSymbolAddress((void**)&h1,      g_h1);
    cudaGetSymbolAddress((void**)&h2,      g_h2);

    // CSR build (once; reused by all 3 layers)
    cudaMemsetAsync(deg, 0, NN * sizeof(int));
    deg_count_kernel<<<(NE + 255) / 256, 256>>>(dst, deg);
    scan_kernel<<<1, 1024>>>(deg, rowptr, cursor);
    fill_csr_kernel<<<(NE + 255) / 256, 256>>>(src, dst, ea, cursor, csr_src, csr_w);

    const float* Wr[3] = {Wrel1, Wrel2, Wrel3};
    const float* Wo[3] = {Wroot1, Wroot2, Wroot3};
    const float* bv[3] = {b1, b2, b3};
    float* outs[3] = {h1, h2, out};

    const float* cur = x;
    int gather_blocks = (NN * 32 + 255) / 256;
    for (int l = 0; l < 3; l++) {
        gather_agg_kernel<<<gather_blocks, 256>>>(cur, rowptr, csr_src, csr_w, agg);
        gemm_fused_kernel<<<(NN + 127) / 128, 256>>>(agg, cur, Wr[l], Wo[l], bv[l], outs[l]);
        cur = outs[l];
    }
}